// round 2
// baseline (speedup 1.0000x reference)
#include <cuda_runtime.h>
#include <cuda_bf16.h>

#define BN 4
#define CH 3
#define HF 544
#define WF 960
#define H2 272
#define W2 480
#define MD 24

__device__ float g_lg[BN*H2*W2];
__device__ float g_rg[BN*H2*W2];
__device__ double g_acc[10];
// 0 anchor_num 1 anchor_den 2 photo_err 3 photo_valid
// 4 sign_sum 5 mag_sum 6 cnt 7 smooth_dx 8 smooth_dy

__global__ void init_kernel(){ if (threadIdx.x < 10) g_acc[threadIdx.x] = 0.0; }

__device__ __forceinline__ float blockReduce(float v, float* buf){
  __syncthreads();
  #pragma unroll
  for (int o=16;o;o>>=1) v += __shfl_down_sync(0xffffffffu, v, o);
  int lane = threadIdx.x & 31, w = threadIdx.x >> 5;
  if (lane==0) buf[w]=v;
  __syncthreads();
  float r = 0.f;
  if (w==0){
    int nw = (blockDim.x + 31) >> 5;
    r = (lane < nw) ? buf[lane] : 0.f;
    #pragma unroll
    for (int o=16;o;o>>=1) r += __shfl_down_sync(0xffffffffu, r, o);
  }
  return r;
}

// ---- half-res grayscale of left/right -------------------------------------
__global__ void down_kernel(const float* __restrict__ left, const float* __restrict__ right){
  int idx = blockIdx.x*blockDim.x + threadIdx.x;
  const int N = BN*H2*W2;
  if (idx >= N) return;
  int x = idx % W2; int t = idx / W2; int y = t % H2; int b = t / H2;
  size_t base = (((size_t)b*CH)*HF + (size_t)(2*y))*WF + (size_t)(2*x);
  float sl = 0.f, sr = 0.f;
  #pragma unroll
  for (int c=0;c<CH;c++){
    size_t o = base + (size_t)c*HF*WF;
    float2 a0 = *(const float2*)(left + o);
    float2 a1 = *(const float2*)(left + o + WF);
    sl += (a0.x + a0.y) + (a1.x + a1.y);
    float2 b0 = *(const float2*)(right + o);
    float2 b1 = *(const float2*)(right + o + WF);
    sr += (b0.x + b0.y) + (b1.x + b1.y);
  }
  g_lg[idx] = sl * (1.f/12.f);
  g_rg[idx] = sr * (1.f/12.f);
}

// ---- GT anchor -------------------------------------------------------------
__global__ void anchor_kernel(const float* __restrict__ pred, const float* __restrict__ gt,
                              const float* __restrict__ conf, const float* __restrict__ occ){
  __shared__ float buf[32];
  const int N = BN*HF*WF;
  float sn=0.f, sd=0.f;
  for (int i = blockIdx.x*blockDim.x + threadIdx.x; i < N; i += gridDim.x*blockDim.x){
    float g = gt[i];
    if (g > 2.0f){
      float t = conf[i]*occ[i];
      sd += t;
      sn += t*fabsf(pred[i]-g);
    }
  }
  float r = blockReduce(sn, buf);
  if (threadIdx.x==0) atomicAdd(&g_acc[0], (double)r);
  r = blockReduce(sd, buf);
  if (threadIdx.x==0) atomicAdd(&g_acc[1], (double)r);
}

// ---- NCC disparity + sign/magnitude ---------------------------------------
__global__ void __launch_bounds__(512) ncc_kernel(const float* __restrict__ pred){
  __shared__ float rgS[11][W2];
  __shared__ float PvS[W2+16];
  __shared__ float colL[W2], colL2[W2], colR[W2], colR2[W2], rmB[W2], rsB[W2];
  __shared__ float buf[32];

  int b = blockIdx.x / H2, y = blockIdx.x % H2;
  int x = threadIdx.x;
  bool ax = (x < W2);

  float lgr[11];
  if (ax){
    float cl=0.f, cl2=0.f, cr=0.f, cr2=0.f;
    #pragma unroll
    for (int r=0;r<11;r++){
      int row = y - 5 + r;
      float lv=0.f, rv=0.f;
      if ((unsigned)row < (unsigned)H2){
        int o = (b*H2+row)*W2 + x;
        lv = g_lg[o]; rv = g_rg[o];
      }
      lgr[r]=lv; rgS[r][x]=rv;
      cl += lv; cl2 = fmaf(lv,lv,cl2); cr += rv; cr2 = fmaf(rv,rv,cr2);
    }
    colL[x]=cl; colL2[x]=cl2; colR[x]=cr; colR2[x]=cr2;
  }
  for (int i=threadIdx.x; i<W2+16; i+=512) PvS[i]=0.f;
  __syncthreads();

  float lm=0.f, lsig=1.f;
  if (ax){
    float sl=0.f, sl2=0.f, sr=0.f, sr2=0.f;
    #pragma unroll
    for (int j=-5;j<=5;j++){
      int xp = x + j;
      if ((unsigned)xp < (unsigned)W2){
        sl += colL[xp]; sl2 += colL2[xp]; sr += colR[xp]; sr2 += colR2[xp];
      }
    }
    lm = sl*(1.f/121.f);
    lsig = sqrtf(fmaxf(sl2*(1.f/121.f) - lm*lm, 1e-8f));
    float rm = sr*(1.f/121.f);
    rmB[x] = rm;
    rsB[x] = sqrtf(fmaxf(sr2*(1.f/121.f) - rm*rm, 1e-8f));
  }
  __syncthreads();

  float best_c = -1.f, best_d = 0.f;
  bool interior = (x >= 5) && (x <= W2-6);

  for (int d=-MD; d<=MD; d++){
    if (d==0) continue;
    int c = x + d;
    bool cin = ((unsigned)c < (unsigned)W2);
    if (ax){
      float pv = 0.f;
      if (cin){
        #pragma unroll
        for (int r=0;r<11;r++) pv = fmaf(lgr[r], rgS[r][c], pv);
      }
      PvS[8+x] = pv;
    }
    __syncthreads();
    if (ax){
      float cs = 0.f;
      #pragma unroll
      for (int j=-5;j<=5;j++) cs += PvS[8+x+j];
      float rm, rs;
      if (interior && cin){
        rm = rmB[c]; rs = rsB[c];
      } else {
        int ra = max(max(c-5, d), 0);
        int rb = min(min(c+5, W2-1+d), W2-1);
        float s1=0.f, s2=0.f;
        for (int cc=ra; cc<=rb; cc++){ s1 += colR[cc]; s2 += colR2[cc]; }
        rm = s1*(1.f/121.f);
        rs = sqrtf(fmaxf(s2*(1.f/121.f) - rm*rm, 1e-8f));
      }
      float ncc = (cs*(1.f/121.f) - lm*rm) / (lsig*rs + 1e-8f);
      if (ncc > best_c){ best_c = ncc; best_d = (float)d; }
    }
    __syncthreads();
  }

  float ss=0.f, sm=0.f, sc=0.f;
  if (ax && best_c > 0.3f){
    float nd = 2.f*best_d;
    float sg = (best_d > 0.f) ? 1.f : -1.f;
    const float* pb = pred + ((size_t)b*HF + (size_t)(2*y))*WF + (size_t)(2*x);
    #pragma unroll
    for (int dy=0;dy<2;dy++)
      #pragma unroll
      for (int dx=0;dx<2;dx++){
        float p = pb[dy*WF + dx];
        ss += fmaxf(-p*sg, 0.f);
        sm += fabsf(p - nd);
      }
    sm *= best_c;
    sc = 4.f;
  }
  float r = blockReduce(ss, buf);
  if (threadIdx.x==0) atomicAdd(&g_acc[4], (double)r);
  r = blockReduce(sm, buf);
  if (threadIdx.x==0) atomicAdd(&g_acc[5], (double)r);
  r = blockReduce(sc, buf);
  if (threadIdx.x==0) atomicAdd(&g_acc[6], (double)r);
}

// ---- photometric (warp + SSIM + L1) ---------------------------------------
#define PTX 32
#define PTY 8
__global__ void __launch_bounds__(256) photo_kernel(const float* __restrict__ pred,
                                                    const float* __restrict__ left,
                                                    const float* __restrict__ right){
  __shared__ float lS[CH][PTY+2][PTX+2];
  __shared__ float wS[CH][PTY+2][PTX+2];
  __shared__ float xsS[PTY+2][PTX+2];
  __shared__ float buf[32];

  int b = blockIdx.z;
  int tx0 = blockIdx.x*PTX, ty0 = blockIdx.y*PTY;
  int tid = threadIdx.x;

  for (int i=tid; i<(PTY+2)*(PTX+2); i+=256){
    int ly = i/(PTX+2), lx = i - ly*(PTX+2);
    int gy = ty0 + ly - 1, gx = tx0 + lx - 1;
    float l0=0.f,l1=0.f,l2=0.f,w0=0.f,w1=0.f,w2=0.f,xs=-1.f;
    if ((unsigned)gy < (unsigned)HF && (unsigned)gx < (unsigned)WF){
      float dv = pred[((size_t)b*HF + gy)*WF + gx];
      xs = (float)gx - dv;
      float xc = fminf(fmaxf(xs, 0.f), (float)(WF-1));
      float x0f = floorf(xc);
      float wt = xc - x0f;
      int x0 = (int)x0f;
      int x1 = min(x0+1, WF-1);
      size_t rb0 = ((size_t)(b*CH)*HF + gy)*WF;
      const float* r0 = right + rb0;
      const float* r1 = r0 + (size_t)HF*WF;
      const float* r2 = r1 + (size_t)HF*WF;
      float omw = 1.f - wt;
      w0 = r0[x0]*omw + r0[x1]*wt;
      w1 = r1[x0]*omw + r1[x1]*wt;
      w2 = r2[x0]*omw + r2[x1]*wt;
      l0 = left[rb0 + gx];
      l1 = left[rb0 + (size_t)HF*WF + gx];
      l2 = left[rb0 + 2*(size_t)HF*WF + gx];
    }
    lS[0][ly][lx]=l0; lS[1][ly][lx]=l1; lS[2][ly][lx]=l2;
    wS[0][ly][lx]=w0; wS[1][ly][lx]=w1; wS[2][ly][lx]=w2;
    xsS[ly][lx]=xs;
  }
  __syncthreads();

  int lx = (tid % PTX) + 1, ly = (tid / PTX) + 1;
  const float C1 = 1e-4f, C2 = 9e-4f;
  float ss_sum = 0.f, l1_sum = 0.f;
  #pragma unroll
  for (int c=0;c<CH;c++){
    float sx=0.f, sy=0.f, sxx=0.f, syy=0.f, sxy=0.f;
    #pragma unroll
    for (int dy=-1;dy<=1;dy++)
      #pragma unroll
      for (int dx=-1;dx<=1;dx++){
        float xv = lS[c][ly+dy][lx+dx];
        float yv = wS[c][ly+dy][lx+dx];
        sx += xv; sy += yv;
        sxx = fmaf(xv,xv,sxx); syy = fmaf(yv,yv,syy); sxy = fmaf(xv,yv,sxy);
      }
    float mx = sx*(1.f/9.f), my = sy*(1.f/9.f);
    float vx = fmaxf(sxx*(1.f/9.f) - mx*mx, 0.f);
    float vy = fmaxf(syy*(1.f/9.f) - my*my, 0.f);
    float vxy = sxy*(1.f/9.f) - mx*my;
    float n = (2.f*mx*my + C1)*(2.f*vxy + C2);
    float den = (mx*mx + my*my + C1)*(vx + vy + C2);
    float dssim = (1.f - n/den)*0.5f;
    ss_sum += fminf(fmaxf(dssim, 0.f), 1.f);
    l1_sum += fabsf(lS[c][ly][lx] - wS[c][ly][lx]);
  }
  float xs = xsS[ly][lx];
  float valid = (xs > 0.f && xs < (float)(WF-1)) ? 1.f : 0.f;
  float err = (0.85f*ss_sum*(1.f/3.f) + 0.15f*l1_sum*(1.f/3.f)) * valid;

  float r = blockReduce(err, buf);
  if (tid==0) atomicAdd(&g_acc[2], (double)r);
  r = blockReduce(valid, buf);
  if (tid==0) atomicAdd(&g_acc[3], (double)r);
}

// ---- smoothness ------------------------------------------------------------
__global__ void smooth_kernel(const float* __restrict__ pred, const float* __restrict__ left){
  __shared__ float buf[32];
  const int N = BN*HF*WF;
  float ax=0.f, ay=0.f;
  for (int i = blockIdx.x*blockDim.x + threadIdx.x; i < N; i += gridDim.x*blockDim.x){
    int x = i % WF; int t = i / WF; int y = t % HF; int b = t / HF;
    size_t p0 = ((size_t)b*HF + y)*WF + x;
    size_t l0 = ((size_t)(b*CH)*HF + y)*WF + x;
    const size_t cs = (size_t)HF*WF;
    float pc = pred[p0];
    if (x < WF-1){
      float dd = fabsf(pred[p0+1] - pc);
      float id = (fabsf(left[l0+1]-left[l0]) + fabsf(left[l0+cs+1]-left[l0+cs])
                + fabsf(left[l0+2*cs+1]-left[l0+2*cs])) * (1.f/3.f);
      ax += dd*__expf(-id);
    }
    if (y < HF-1){
      float dd = fabsf(pred[p0+WF] - pc);
      float id = (fabsf(left[l0+WF]-left[l0]) + fabsf(left[l0+cs+WF]-left[l0+cs])
                + fabsf(left[l0+2*cs+WF]-left[l0+2*cs])) * (1.f/3.f);
      ay += dd*__expf(-id);
    }
  }
  float r = blockReduce(ax, buf);
  if (threadIdx.x==0) atomicAdd(&g_acc[7], (double)r);
  r = blockReduce(ay, buf);
  if (threadIdx.x==0) atomicAdd(&g_acc[8], (double)r);
}

// ---- finalize --------------------------------------------------------------
__global__ void final_kernel(float* out){
  double anchor = g_acc[0] / fmax(g_acc[1], 1.0);
  double photo  = g_acc[2] / fmax(g_acc[3], 1.0);
  double n      = fmax(g_acc[6], 1.0);
  double smag   = 0.3*(g_acc[4]/n) + 0.7*(g_acc[5]/n);
  double sdx    = g_acc[7] / ((double)BN*HF*(WF-1));
  double sdy    = g_acc[8] / ((double)BN*(HF-1)*WF);
  out[0] = (float)(anchor + photo + 0.5*smag + 0.1*(sdx + sdy));
}

extern "C" void kernel_launch(void* const* d_in, const int* in_sizes, int n_in,
                              void* d_out, int out_size) {
  const float* pred  = (const float*)d_in[0];
  const float* gt    = (const float*)d_in[1];
  const float* conf  = (const float*)d_in[2];
  const float* occ   = (const float*)d_in[3];
  const float* left  = (const float*)d_in[4];
  const float* right = (const float*)d_in[5];
  float* out = (float*)d_out;

  init_kernel<<<1, 32>>>();
  {
    int N = BN*H2*W2;
    down_kernel<<<(N+255)/256, 256>>>(left, right);
  }
  anchor_kernel<<<1024, 256>>>(pred, gt, conf, occ);
  ncc_kernel<<<BN*H2, 512>>>(pred);
  {
    dim3 g(WF/PTX, HF/PTY, BN);
    photo_kernel<<<g, 256>>>(pred, left, right);
  }
  smooth_kernel<<<1024, 256>>>(pred, left);
  final_kernel<<<1, 1>>>(out);
}

// round 7
// speedup vs baseline: 1.0189x; 1.0189x over previous
#include <cuda_runtime.h>
#include <cuda_bf16.h>

#define BN 4
#define CH 3
#define HF 544
#define WF 960
#define H2 272
#define W2 480
#define MD 24
#define DB 6        // disparities per barrier phase

__device__ float g_lg[BN*H2*W2];
__device__ float g_rg[BN*H2*W2];
__device__ double g_acc[10];
// 0 anchor_num 1 anchor_den 2 photo_err 3 photo_valid
// 4 sign_sum 5 mag_sum 6 cnt 7 smooth_dx 8 smooth_dy

__global__ void init_kernel(){ if (threadIdx.x < 10) g_acc[threadIdx.x] = 0.0; }

__device__ __forceinline__ float blockReduce(float v, float* buf){
  __syncthreads();
  #pragma unroll
  for (int o=16;o;o>>=1) v += __shfl_down_sync(0xffffffffu, v, o);
  int lane = threadIdx.x & 31, w = threadIdx.x >> 5;
  if (lane==0) buf[w]=v;
  __syncthreads();
  float r = 0.f;
  if (w==0){
    int nw = (blockDim.x + 31) >> 5;
    r = (lane < nw) ? buf[lane] : 0.f;
    #pragma unroll
    for (int o=16;o;o>>=1) r += __shfl_down_sync(0xffffffffu, r, o);
  }
  return r;
}

// ---- half-res grayscale of left/right -------------------------------------
__global__ void down_kernel(const float* __restrict__ left, const float* __restrict__ right){
  int idx = blockIdx.x*blockDim.x + threadIdx.x;
  const int N = BN*H2*W2;
  if (idx >= N) return;
  int x = idx % W2; int t = idx / W2; int y = t % H2; int b = t / H2;
  size_t base = (((size_t)b*CH)*HF + (size_t)(2*y))*WF + (size_t)(2*x);
  float sl = 0.f, sr = 0.f;
  #pragma unroll
  for (int c=0;c<CH;c++){
    size_t o = base + (size_t)c*HF*WF;
    float2 a0 = *(const float2*)(left + o);
    float2 a1 = *(const float2*)(left + o + WF);
    sl += (a0.x + a0.y) + (a1.x + a1.y);
    float2 b0 = *(const float2*)(right + o);
    float2 b1 = *(const float2*)(right + o + WF);
    sr += (b0.x + b0.y) + (b1.x + b1.y);
  }
  g_lg[idx] = sl * (1.f/12.f);
  g_rg[idx] = sr * (1.f/12.f);
}

// ---- fused GT anchor + smoothness ------------------------------------------
__global__ void anchor_smooth_kernel(const float* __restrict__ pred, const float* __restrict__ gt,
                                     const float* __restrict__ conf, const float* __restrict__ occ,
                                     const float* __restrict__ left){
  __shared__ float buf[32];
  const int N = BN*HF*WF;
  const size_t cs = (size_t)HF*WF;
  float sn=0.f, sd=0.f, axs=0.f, ays=0.f;
  for (int i = blockIdx.x*blockDim.x + threadIdx.x; i < N; i += gridDim.x*blockDim.x){
    int x = i % WF; int t = i / WF; int y = t % HF; int b = t / HF;
    float g = gt[i];
    float pc = pred[i];
    if (g > 2.0f){
      float tt = conf[i]*occ[i];
      sd += tt;
      sn += tt*fabsf(pc-g);
    }
    size_t l0 = ((size_t)(b*CH)*HF + y)*WF + x;
    if (x < WF-1){
      float dd = fabsf(pred[i+1] - pc);
      float id = (fabsf(left[l0+1]-left[l0]) + fabsf(left[l0+cs+1]-left[l0+cs])
                + fabsf(left[l0+2*cs+1]-left[l0+2*cs])) * (1.f/3.f);
      axs += dd*__expf(-id);
    }
    if (y < HF-1){
      float dd = fabsf(pred[i+WF] - pc);
      float id = (fabsf(left[l0+WF]-left[l0]) + fabsf(left[l0+cs+WF]-left[l0+cs])
                + fabsf(left[l0+2*cs+WF]-left[l0+2*cs])) * (1.f/3.f);
      ays += dd*__expf(-id);
    }
  }
  float r = blockReduce(sn, buf);
  if (threadIdx.x==0) atomicAdd(&g_acc[0], (double)r);
  r = blockReduce(sd, buf);
  if (threadIdx.x==0) atomicAdd(&g_acc[1], (double)r);
  r = blockReduce(axs, buf);
  if (threadIdx.x==0) atomicAdd(&g_acc[7], (double)r);
  r = blockReduce(ays, buf);
  if (threadIdx.x==0) atomicAdd(&g_acc[8], (double)r);
}

// ---- NCC disparity + sign/magnitude ---------------------------------------
// one block per (b, half-res row). 6 disparities per barrier phase.
__global__ void __launch_bounds__(512,2) ncc_kernel(const float* __restrict__ pred){
  __shared__ float rgS[11][W2+48];   // offset 24, zero-padded
  __shared__ float PvS[DB][W2+16];   // offset 8, zero-padded
  __shared__ float colLp[W2+16];     // offset 8
  __shared__ float colL2p[W2+16];
  __shared__ float colRp[W2+64];     // offset 32
  __shared__ float colR2p[W2+64];
  __shared__ float rmB[W2+48];       // offset 24: stats for shifted-window center c
  __shared__ float rsB[W2+48];
  __shared__ float buf[32];

  int b = blockIdx.x / H2, y = blockIdx.x % H2;
  int x = threadIdx.x;
  int tid = threadIdx.x;
  bool ax = (x < W2);

  // halo zero-init — stride loops so ALL pad elements are covered by 512 threads
  for (int t2 = tid; t2 < 11*48; t2 += 512){
    int r = t2/48, i = t2%48;
    rgS[r][ i<24 ? i : 504+(i-24) ] = 0.f;
  }
  for (int t2 = tid; t2 < DB*16; t2 += 512){
    int k = t2/16, i = t2%16;
    PvS[k][ i<8 ? i : 488+(i-8) ] = 0.f;
  }
  for (int t2 = tid; t2 < 16; t2 += 512){
    int idx = t2<8 ? t2 : 480+t2;
    colLp[idx]=0.f; colL2p[idx]=0.f;
  }
  for (int t2 = tid; t2 < 64; t2 += 512){
    int idx = t2<32 ? t2 : 480+t2;
    colRp[idx]=0.f; colR2p[idx]=0.f;
  }

  float lgr[11];
  if (ax){
    float cl=0.f, cl2=0.f, cr=0.f, cr2=0.f;
    #pragma unroll
    for (int r=0;r<11;r++){
      int row = y - 5 + r;
      float lv=0.f, rv=0.f;
      if ((unsigned)row < (unsigned)H2){
        int o = (b*H2+row)*W2 + x;
        lv = g_lg[o]; rv = g_rg[o];
      }
      lgr[r]=lv; rgS[r][24+x]=rv;
      cl += lv; cl2 = fmaf(lv,lv,cl2); cr += rv; cr2 = fmaf(rv,rv,cr2);
    }
    colLp[8+x]=cl; colL2p[8+x]=cl2; colRp[32+x]=cr; colR2p[32+x]=cr2;
  }
  __syncthreads();

  // left stats (per thread) + right stats table for all shifted centers c in [-24, 504)
  float lm=0.f, lsig=1.f;
  if (ax){
    float sl=0.f, sl2=0.f;
    #pragma unroll
    for (int j=0;j<11;j++){ sl += colLp[3+x+j]; sl2 += colL2p[3+x+j]; }
    lm = sl*(1.f/121.f);
    lsig = sqrtf(fmaxf(sl2*(1.f/121.f) - lm*lm, 1e-8f));
  }
  for (int idx = tid; idx < W2+48; idx += 512){
    // center c = idx - 24; window columns c-5..c+5 -> colRp index 32+c+j-5 = 3+idx+j
    float s1=0.f, s2=0.f;
    #pragma unroll
    for (int j=0;j<11;j++){ s1 += colRp[3+idx+j]; s2 += colR2p[3+idx+j]; }
    float rm = s1*(1.f/121.f);
    rmB[idx] = rm;
    rsB[idx] = sqrtf(fmaxf(s2*(1.f/121.f) - rm*rm, 1e-8f));
  }
  __syncthreads();

  float best_c = -1.f, best_d = 0.f;
  bool interior = (x >= 5) && (x <= W2-6);

  #pragma unroll 1
  for (int phase = 0; phase < 8; phase++){
    int dstart = (phase < 4) ? (-24 + phase*DB) : (1 + (phase-4)*DB);
    if (ax){
      float pv[DB];
      #pragma unroll
      for (int k=0;k<DB;k++) pv[k]=0.f;
      const int cb = 24 + x + dstart;       // rgS index base
      #pragma unroll
      for (int r=0;r<11;r++){
        float lv = lgr[r];
        #pragma unroll
        for (int k=0;k<DB;k++) pv[k] = fmaf(lv, rgS[r][cb+k], pv[k]);
      }
      #pragma unroll
      for (int k=0;k<DB;k++) PvS[k][8+x] = pv[k];
    }
    __syncthreads();
    if (ax){
      #pragma unroll
      for (int k=0;k<DB;k++){
        float cs = 0.f;
        #pragma unroll
        for (int j=0;j<11;j++) cs += PvS[k][3+x+j];
        int d = dstart + k;
        int c = x + d;
        float rm, rs;
        if (interior){
          rm = rmB[24+c]; rs = rsB[24+c];
        } else {
          int ra = max(max(c-5, d), 0);
          int rb = min(min(c+5, W2-1+d), W2-1);
          float s1=0.f, s2=0.f;
          for (int cc=ra; cc<=rb; cc++){ s1 += colRp[32+cc]; s2 += colR2p[32+cc]; }
          rm = s1*(1.f/121.f);
          rs = sqrtf(fmaxf(s2*(1.f/121.f) - rm*rm, 1e-8f));
        }
        float ncc = (cs*(1.f/121.f) - lm*rm) / (lsig*rs + 1e-8f);
        if (ncc > best_c){ best_c = ncc; best_d = (float)d; }
      }
    }
    __syncthreads();
  }

  float ss=0.f, sm=0.f, sc=0.f;
  if (ax && best_c > 0.3f){
    float nd = 2.f*best_d;
    float sg = (best_d > 0.f) ? 1.f : -1.f;
    const float* pb = pred + ((size_t)b*HF + (size_t)(2*y))*WF + (size_t)(2*x);
    #pragma unroll
    for (int dy=0;dy<2;dy++)
      #pragma unroll
      for (int dx=0;dx<2;dx++){
        float p = pb[dy*WF + dx];
        ss += fmaxf(-p*sg, 0.f);
        sm += fabsf(p - nd);
      }
    sm *= best_c;
    sc = 4.f;
  }
  float r = blockReduce(ss, buf);
  if (threadIdx.x==0) atomicAdd(&g_acc[4], (double)r);
  r = blockReduce(sm, buf);
  if (threadIdx.x==0) atomicAdd(&g_acc[5], (double)r);
  r = blockReduce(sc, buf);
  if (threadIdx.x==0) atomicAdd(&g_acc[6], (double)r);
}

// ---- photometric (warp + SSIM + L1) ---------------------------------------
#define PTX 32
#define PTY 8
__global__ void __launch_bounds__(256) photo_kernel(const float* __restrict__ pred,
                                                    const float* __restrict__ left,
                                                    const float* __restrict__ right){
  __shared__ float lS[CH][PTY+2][PTX+2];
  __shared__ float wS[CH][PTY+2][PTX+2];
  __shared__ float xsS[PTY+2][PTX+2];
  __shared__ float buf[32];

  int b = blockIdx.z;
  int tx0 = blockIdx.x*PTX, ty0 = blockIdx.y*PTY;
  int tid = threadIdx.x;

  for (int i=tid; i<(PTY+2)*(PTX+2); i+=256){
    int ly = i/(PTX+2), lx = i - ly*(PTX+2);
    int gy = ty0 + ly - 1, gx = tx0 + lx - 1;
    float l0=0.f,l1=0.f,l2=0.f,w0=0.f,w1=0.f,w2=0.f,xs=-1.f;
    if ((unsigned)gy < (unsigned)HF && (unsigned)gx < (unsigned)WF){
      float dv = pred[((size_t)b*HF + gy)*WF + gx];
      xs = (float)gx - dv;
      float xc = fminf(fmaxf(xs, 0.f), (float)(WF-1));
      float x0f = floorf(xc);
      float wt = xc - x0f;
      int x0 = (int)x0f;
      int x1 = min(x0+1, WF-1);
      size_t rb0 = ((size_t)(b*CH)*HF + gy)*WF;
      const float* r0 = right + rb0;
      const float* r1 = r0 + (size_t)HF*WF;
      const float* r2 = r1 + (size_t)HF*WF;
      float omw = 1.f - wt;
      w0 = r0[x0]*omw + r0[x1]*wt;
      w1 = r1[x0]*omw + r1[x1]*wt;
      w2 = r2[x0]*omw + r2[x1]*wt;
      l0 = left[rb0 + gx];
      l1 = left[rb0 + (size_t)HF*WF + gx];
      l2 = left[rb0 + 2*(size_t)HF*WF + gx];
    }
    lS[0][ly][lx]=l0; lS[1][ly][lx]=l1; lS[2][ly][lx]=l2;
    wS[0][ly][lx]=w0; wS[1][ly][lx]=w1; wS[2][ly][lx]=w2;
    xsS[ly][lx]=xs;
  }
  __syncthreads();

  int lx = (tid % PTX) + 1, ly = (tid / PTX) + 1;
  const float C1 = 1e-4f, C2 = 9e-4f;
  float ss_sum = 0.f, l1_sum = 0.f;
  #pragma unroll
  for (int c=0;c<CH;c++){
    float sx=0.f, sy=0.f, sxx=0.f, syy=0.f, sxy=0.f;
    #pragma unroll
    for (int dy=-1;dy<=1;dy++)
      #pragma unroll
      for (int dx=-1;dx<=1;dx++){
        float xv = lS[c][ly+dy][lx+dx];
        float yv = wS[c][ly+dy][lx+dx];
        sx += xv; sy += yv;
        sxx = fmaf(xv,xv,sxx); syy = fmaf(yv,yv,syy); sxy = fmaf(xv,yv,sxy);
      }
    float mx = sx*(1.f/9.f), my = sy*(1.f/9.f);
    float vx = fmaxf(sxx*(1.f/9.f) - mx*mx, 0.f);
    float vy = fmaxf(syy*(1.f/9.f) - my*my, 0.f);
    float vxy = sxy*(1.f/9.f) - mx*my;
    float n = (2.f*mx*my + C1)*(2.f*vxy + C2);
    float den = (mx*mx + my*my + C1)*(vx + vy + C2);
    float dssim = (1.f - n/den)*0.5f;
    ss_sum += fminf(fmaxf(dssim, 0.f), 1.f);
    l1_sum += fabsf(lS[c][ly][lx] - wS[c][ly][lx]);
  }
  float xs = xsS[ly][lx];
  float valid = (xs > 0.f && xs < (float)(WF-1)) ? 1.f : 0.f;
  float err = (0.85f*ss_sum*(1.f/3.f) + 0.15f*l1_sum*(1.f/3.f)) * valid;

  float r = blockReduce(err, buf);
  if (tid==0) atomicAdd(&g_acc[2], (double)r);
  r = blockReduce(valid, buf);
  if (tid==0) atomicAdd(&g_acc[3], (double)r);
}

// ---- finalize --------------------------------------------------------------
__global__ void final_kernel(float* out){
  double anchor = g_acc[0] / fmax(g_acc[1], 1.0);
  double photo  = g_acc[2] / fmax(g_acc[3], 1.0);
  double n      = fmax(g_acc[6], 1.0);
  double smag   = 0.3*(g_acc[4]/n) + 0.7*(g_acc[5]/n);
  double sdx    = g_acc[7] / ((double)BN*HF*(WF-1));
  double sdy    = g_acc[8] / ((double)BN*(HF-1)*WF);
  out[0] = (float)(anchor + photo + 0.5*smag + 0.1*(sdx + sdy));
}

extern "C" void kernel_launch(void* const* d_in, const int* in_sizes, int n_in,
                              void* d_out, int out_size) {
  const float* pred  = (const float*)d_in[0];
  const float* gt    = (const float*)d_in[1];
  const float* conf  = (const float*)d_in[2];
  const float* occ   = (const float*)d_in[3];
  const float* left  = (const float*)d_in[4];
  const float* right = (const float*)d_in[5];
  float* out = (float*)d_out;

  init_kernel<<<1, 32>>>();
  {
    int N = BN*H2*W2;
    down_kernel<<<(N+255)/256, 256>>>(left, right);
  }
  anchor_smooth_kernel<<<1024, 256>>>(pred, gt, conf, occ, left);
  ncc_kernel<<<BN*H2, 512>>>(pred);
  {
    dim3 g(WF/PTX, HF/PTY, BN);
    photo_kernel<<<g, 256>>>(pred, left, right);
  }
  final_kernel<<<1, 1>>>(out);
}